// round 8
// baseline (speedup 1.0000x reference)
#include <cuda_runtime.h>
#include <cuda_bf16.h>

#define BB     128
#define NTOK   1369
#define DINOD  384
#define CLIPD  512
#define NH     8
#define NSLICE 8
#define SLTOK  172                      // ceil(1369/8)

__device__ __align__(16) float g_Q[BB*CLIPD];
__device__ __align__(16) float g_qk[BB*NH*DINOD];
__device__ __align__(16) float g_att[BB*NH*NTOK];        // logits [b][h][n]
__device__ __align__(16) float g_attT[BB*NTOK*NH];       // normalized attn [b][n][h]
__device__ __align__(16) float g_part[NSLICE*BB*DINOD*NH]; // partial ctx [s][b][c][h]

// ---- packed f32x2 helpers ----
__device__ __forceinline__ unsigned long long pk2(float x, float y){
  unsigned long long r; asm("mov.b64 %0, {%1,%2};" : "=l"(r) : "f"(x), "f"(y)); return r;
}
__device__ __forceinline__ float2 upk2(unsigned long long v){
  float2 r; asm("mov.b64 {%0,%1}, %2;" : "=f"(r.x), "=f"(r.y) : "l"(v)); return r;
}
__device__ __forceinline__ void fma2(unsigned long long& d, unsigned long long a, unsigned long long b){
  asm("fma.rn.f32x2 %0, %1, %2, %0;" : "+l"(d) : "l"(a), "l"(b));
}

// ============ K1: Q = clip @ Wq + bq ============
__global__ void __launch_bounds__(128) k1_qproj(const float* __restrict__ clip,
                                                const float* __restrict__ Wq,
                                                const float* __restrict__ bq){
  __shared__ float cs[2][CLIPD];
  int t = threadIdx.x;
  int p = blockIdx.x >> 1, half = blockIdx.x & 1;
  int b0 = 2*p, b1 = 2*p + 1;
  for(int i = t; i < CLIPD; i += 128){
    cs[0][i] = clip[(size_t)b0*CLIPD + i];
    cs[1][i] = clip[(size_t)b1*CLIPD + i];
  }
  __syncthreads();
  int col = half*256 + 2*t;
  float2 bq2 = *(const float2*)(bq + col);
  unsigned long long A0 = pk2(bq2.x, bq2.y), A1 = A0;
  #pragma unroll 8
  for(int c = 0; c < CLIPD; c++){
    float2 w = *(const float2*)(Wq + (size_t)c*CLIPD + col);
    unsigned long long wp = pk2(w.x, w.y);
    float c0 = cs[0][c], c1 = cs[1][c];
    fma2(A0, wp, pk2(c0, c0));
    fma2(A1, wp, pk2(c1, c1));
  }
  *(float2*)(g_Q + (size_t)b0*CLIPD + col) = upk2(A0);
  *(float2*)(g_Q + (size_t)b1*CLIPD + col) = upk2(A1);
}

// ============ K2: qk[b,h,c] = sum_d Wk[c,h*64+d]*Q[b,h*64+d] / (8*temp) ============
__global__ void __launch_bounds__(384) k2_qk(const float* __restrict__ Wk,
                                             const float* __restrict__ temp){
  __shared__ float Qs[2][CLIPD];
  int t = threadIdx.x;
  int b0 = blockIdx.x * 2;
  for(int i = t; i < 2*CLIPD; i += 384) Qs[i>>9][i&511] = g_Q[(size_t)b0*CLIPD + i];
  __syncthreads();
  float inv_scale = 1.0f/(8.0f*temp[0]);
  int w = t>>5, l = t&31;
  for(int c = w; c < DINOD; c += 12){
    const float* wr = Wk + (size_t)c*CLIPD;
    #pragma unroll
    for(int h = 0; h < NH; h++){
      float w0 = wr[h*64 + l], w1 = wr[h*64 + 32 + l];
      #pragma unroll
      for(int bb = 0; bb < 2; bb++){
        float s = w0*Qs[bb][h*64+l] + w1*Qs[bb][h*64+32+l];
        #pragma unroll
        for(int o = 16; o; o >>= 1) s += __shfl_xor_sync(0xffffffffu, s, o);
        if(l == 0) g_qk[((size_t)(b0+bb)*NH + h)*DINOD + c] = s*inv_scale;
      }
    }
  }
}

// ============ K3a: logits[b][h][n] = dino[b,n,:] . qk[b,h,:] ============
// grid 1024 = 128 b x 8 slices; 256 thr = 8 warps; NO smem, NO barriers.
// Warp group wg=wid>>2: heads wg*4..+3. Token stride 4 within slice (wtok=wid&3).
// Lane: hl=lane&15 owns c = j*64 + hl*4 (j=0..5); lane half picks head pair.
__global__ void __launch_bounds__(256, 2) k3a_logits(const float* __restrict__ dino){
  int t = threadIdx.x, wid = t>>5, lane = t&31;
  int b = blockIdx.x >> 3, slice = blockIdx.x & 7;
  int start = slice*SLTOK;
  int end = min(start + SLTOK, NTOK);
  int wg = wid>>2, wtok = wid&3;
  int hl = lane & 15;
  int h0 = wg*4 + (lane>>4)*2;
  const float* dino_b = dino + (size_t)b*NTOK*DINOD;

  unsigned long long q0[6][2], q1[6][2];
  {
    const float* qkb = g_qk + (size_t)b*NH*DINOD;
    #pragma unroll
    for(int j = 0; j < 6; j++){
      float4 v = *(const float4*)(qkb + h0*DINOD + j*64 + hl*4);
      q0[j][0] = pk2(v.x,v.y); q0[j][1] = pk2(v.z,v.w);
      float4 u = *(const float4*)(qkb + (h0+1)*DINOD + j*64 + hl*4);
      q1[j][0] = pk2(u.x,u.y); q1[j][1] = pk2(u.z,u.w);
    }
  }
  float* att0 = g_att + ((size_t)b*NH + h0)*NTOK;
  float* att1 = att0 + NTOK;

  for(int n = start + wtok; n < end; n += 4){
    const float4* rf = (const float4*)(dino_b + (size_t)n*DINOD);
    unsigned long long s0p = 0ull, s1p = 0ull;
    #pragma unroll
    for(int j = 0; j < 6; j++){
      float4 d = rf[j*16 + hl];
      unsigned long long dA = pk2(d.x,d.y), dB = pk2(d.z,d.w);
      fma2(s0p, dA, q0[j][0]); fma2(s0p, dB, q0[j][1]);
      fma2(s1p, dA, q1[j][0]); fma2(s1p, dB, q1[j][1]);
    }
    float2 P0 = upk2(s0p), P1 = upk2(s1p);
    float s0 = P0.x + P0.y, s1 = P1.x + P1.y;
    #pragma unroll
    for(int o = 8; o; o >>= 1){
      s0 += __shfl_xor_sync(0xffffffffu, s0, o);
      s1 += __shfl_xor_sync(0xffffffffu, s1, o);
    }
    if(hl == 0){ att0[n] = s0; att1[n] = s1; }
  }
}

// ============ K3b: softmax per (b,h), write normalized TRANSPOSED attn ============
// grid 128 (per b), 256 thr = 8 warps; warp w owns head w.
__global__ void __launch_bounds__(256) k3b_softmax(){
  __shared__ float sa[NH*NTOK];     // 43808 B
  __shared__ float inv_s[NH];
  int t = threadIdx.x, wid = t>>5, lane = t&31;
  int b = blockIdx.x;
  const float* src = g_att + (size_t)b*NH*NTOK;
  for(int i = t; i < NH*NTOK; i += 256) sa[i] = src[i];
  __syncthreads();
  {
    float* row = sa + wid*NTOK;
    float v = -1e30f;
    for(int n = lane; n < NTOK; n += 32) v = fmaxf(v, row[n]);
    #pragma unroll
    for(int o = 16; o; o >>= 1) v = fmaxf(v, __shfl_xor_sync(0xffffffffu, v, o));
    float m = v;
    float s = 0.0f;
    for(int n = lane; n < NTOK; n += 32){
      float e = __expf(row[n] - m);
      row[n] = e;
      s += e;
    }
    #pragma unroll
    for(int o = 16; o; o >>= 1) s += __shfl_xor_sync(0xffffffffu, s, o);
    if(lane == 0) inv_s[wid] = 1.0f/s;
  }
  __syncthreads();
  float i0 = inv_s[0], i1 = inv_s[1], i2 = inv_s[2], i3 = inv_s[3];
  float i4 = inv_s[4], i5 = inv_s[5], i6 = inv_s[6], i7 = inv_s[7];
  for(int n = t; n < NTOK; n += 256){
    float4 lo = make_float4(sa[0*NTOK+n]*i0, sa[1*NTOK+n]*i1, sa[2*NTOK+n]*i2, sa[3*NTOK+n]*i3);
    float4 hi = make_float4(sa[4*NTOK+n]*i4, sa[5*NTOK+n]*i5, sa[6*NTOK+n]*i6, sa[7*NTOK+n]*i7);
    float4* dst = (float4*)(g_attT + ((size_t)b*NTOK + n)*NH);
    dst[0] = lo; dst[1] = hi;
  }
}

// ============ K3c: partial ctx[s][b][c][h] = sum_{n in slice} attn[b][n][h]*dino[b][n][c] ============
// grid 1024 = 128 b x 8 slices; 128 thr; thread owns cols {t, t+128, t+256}; no barriers.
__global__ void __launch_bounds__(128) k3c_ctx(const float* __restrict__ dino){
  int t = threadIdx.x;
  int b = blockIdx.x >> 3, slice = blockIdx.x & 7;
  int start = slice*SLTOK;
  int end = min(start + SLTOK, NTOK);
  const float* dino_b = dino + (size_t)b*NTOK*DINOD;
  unsigned long long acc[3][4];
  #pragma unroll
  for(int k = 0; k < 3; k++)
    #pragma unroll
    for(int j = 0; j < 4; j++) acc[k][j] = 0ull;

  for(int n = start; n < end; n++){
    const float4* ap = (const float4*)(g_attT + ((size_t)b*NTOK + n)*NH);
    float4 aL = ap[0], aH = ap[1];
    unsigned long long A0 = pk2(aL.x,aL.y), A1 = pk2(aL.z,aL.w);
    unsigned long long A2 = pk2(aH.x,aH.y), A3 = pk2(aH.z,aH.w);
    const float* dr = dino_b + (size_t)n*DINOD;
    float d0 = dr[t], d1 = dr[t+128], d2 = dr[t+256];
    unsigned long long D0 = pk2(d0,d0), D1 = pk2(d1,d1), D2 = pk2(d2,d2);
    fma2(acc[0][0], A0, D0); fma2(acc[0][1], A1, D0);
    fma2(acc[0][2], A2, D0); fma2(acc[0][3], A3, D0);
    fma2(acc[1][0], A0, D1); fma2(acc[1][1], A1, D1);
    fma2(acc[1][2], A2, D1); fma2(acc[1][3], A3, D1);
    fma2(acc[2][0], A0, D2); fma2(acc[2][1], A1, D2);
    fma2(acc[2][2], A2, D2); fma2(acc[2][3], A3, D2);
  }
  float* pb = g_part + ((size_t)(slice*BB + b))*DINOD*NH;
  #pragma unroll
  for(int k = 0; k < 3; k++){
    int c = t + k*128;
    float2 p0 = upk2(acc[k][0]), p1 = upk2(acc[k][1]);
    float2 p2 = upk2(acc[k][2]), p3 = upk2(acc[k][3]);
    float4* dst = (float4*)(pb + (size_t)c*NH);
    dst[0] = make_float4(p0.x, p0.y, p1.x, p1.y);
    dst[1] = make_float4(p2.x, p2.y, p3.x, p3.y);
  }
}

// ============ K4: merge partials, out = ctx @ Wv + bv, LayerNorm ============
// grid 128 (per b), 1024 thr: cg = t>>9 splits the c-reduction in half.
__global__ void __launch_bounds__(1024) k4_out(const float* __restrict__ Wv,
                                               const float* __restrict__ bv,
                                               const float* __restrict__ gamma,
                                               const float* __restrict__ beta,
                                               float* __restrict__ out){
  __shared__ float cs[DINOD*NH];   // ctx, layout [c][h]
  __shared__ float red2[CLIPD];
  __shared__ float redS[16], redQ[16];
  __shared__ float stats[2];
  int t = threadIdx.x;
  int b = blockIdx.x;
  // merge 8 slice partials
  for(int i = t; i < DINOD*NH; i += 1024){
    float a = 0.0f;
    #pragma unroll
    for(int s = 0; s < NSLICE; s++)
      a += g_part[((size_t)(s*BB + b))*DINOD*NH + i];
    cs[i] = a;
  }
  __syncthreads();
  int cg = t >> 9, col = t & 511, h = col >> 6;
  float acc = cg ? 0.0f : bv[col];
  {
    int c0 = cg*192;
    const float* wp = Wv + (size_t)c0*CLIPD + col;
    const float* cp = cs + c0*NH + h;
    #pragma unroll 8
    for(int c = 0; c < 192; c++){
      acc = fmaf(cp[c*NH], wp[(size_t)c*CLIPD], acc);
    }
  }
  if(cg) red2[col] = acc;
  __syncthreads();
  float a = 0.0f;
  if(!cg){
    a = acc + red2[col];
    float s = a, q = a*a;
    #pragma unroll
    for(int o = 16; o; o >>= 1){
      s += __shfl_xor_sync(0xffffffffu, s, o);
      q += __shfl_xor_sync(0xffffffffu, q, o);
    }
    if((t&31) == 0){ redS[t>>5] = s; redQ[t>>5] = q; }
  }
  __syncthreads();
  if(t < 32){
    float v = (t < 16) ? redS[t] : redQ[t-16];
    #pragma unroll
    for(int o = 8; o; o >>= 1) v += __shfl_xor_sync(0xffffffffu, v, o);
    if(t == 0)  stats[0] = v;
    if(t == 16) stats[1] = v;
  }
  __syncthreads();
  if(!cg){
    float mu = stats[0]*(1.0f/512.0f);
    float var = stats[1]*(1.0f/512.0f) - mu*mu;
    float rstd = rsqrtf(var + 1e-5f);
    out[(size_t)b*CLIPD + col] = (a - mu)*rstd*gamma[col] + beta[col];
  }
}

extern "C" void kernel_launch(void* const* d_in, const int* in_sizes, int n_in,
                              void* d_out, int out_size) {
  const float* dino  = (const float*)d_in[0];
  const float* clip  = (const float*)d_in[1];
  const float* Wq    = (const float*)d_in[2];
  const float* bq    = (const float*)d_in[3];
  const float* Wk    = (const float*)d_in[4];
  // d_in[5] = bk: cancels in softmax
  const float* Wv    = (const float*)d_in[6];
  const float* bv    = (const float*)d_in[7];
  const float* temp  = (const float*)d_in[8];
  const float* gamma = (const float*)d_in[9];
  const float* beta  = (const float*)d_in[10];
  float* out = (float*)d_out;

  k1_qproj<<<128, 128>>>(clip, Wq, bq);
  k2_qk<<<64, 384>>>(Wk, temp);
  k3a_logits<<<BB*NSLICE, 256>>>(dino);
  k3b_softmax<<<BB, 256>>>();
  k3c_ctx<<<BB*NSLICE, 128>>>(dino);
  k4_out<<<BB, 1024>>>(Wv, bv, gamma, beta, out);
}

// round 9
// speedup vs baseline: 1.0993x; 1.0993x over previous
#include <cuda_runtime.h>
#include <cuda_bf16.h>

#define BB     128
#define NTOK   1369
#define NTOKP  1372          // padded row length (16B-aligned rows)
#define DINOD  384
#define CLIPD  512
#define NH     8
#define NSL    8             // ctx slices
#define SLTOK  172           // tokens per ctx slice (last = 165)
#define ASL    11            // logits slices of 128 tokens

__device__ __align__(16) float g_Q[BB*CLIPD];
__device__ __align__(16) float g_qk[BB*NH*DINOD];
__device__ __align__(16) float g_att[BB*NH*NTOKP];        // raw logits [b][h][n]
__device__ __align__(16) float g_ml[BB*16];               // per b: m[0..7], l[8..15]
__device__ __align__(16) float g_part[NSL*BB*DINOD*NH];   // partial ctx [s][b][c][h]

// ---- packed f32x2 helpers ----
__device__ __forceinline__ unsigned long long pk2(float x, float y){
  unsigned long long r; asm("mov.b64 %0, {%1,%2};" : "=l"(r) : "f"(x), "f"(y)); return r;
}
__device__ __forceinline__ float2 upk2(unsigned long long v){
  float2 r; asm("mov.b64 {%0,%1}, %2;" : "=f"(r.x), "=f"(r.y) : "l"(v)); return r;
}
__device__ __forceinline__ void fma2(unsigned long long& d, unsigned long long a, unsigned long long b){
  asm("fma.rn.f32x2 %0, %1, %2, %0;" : "+l"(d) : "l"(a), "l"(b));
}

// ============ K1: Q = clip @ Wq + bq ============
__global__ void __launch_bounds__(128) k1_qproj(const float* __restrict__ clip,
                                                const float* __restrict__ Wq,
                                                const float* __restrict__ bq){
  __shared__ float cs[2][CLIPD];
  int t = threadIdx.x;
  int p = blockIdx.x >> 1, half = blockIdx.x & 1;
  int b0 = 2*p, b1 = 2*p + 1;
  for(int i = t; i < CLIPD; i += 128){
    cs[0][i] = clip[(size_t)b0*CLIPD + i];
    cs[1][i] = clip[(size_t)b1*CLIPD + i];
  }
  __syncthreads();
  int col = half*256 + 2*t;
  float2 bq2 = *(const float2*)(bq + col);
  unsigned long long A0 = pk2(bq2.x, bq2.y), A1 = A0;
  #pragma unroll 8
  for(int c = 0; c < CLIPD; c++){
    float2 w = *(const float2*)(Wq + (size_t)c*CLIPD + col);
    unsigned long long wp = pk2(w.x, w.y);
    float c0 = cs[0][c], c1 = cs[1][c];
    fma2(A0, wp, pk2(c0, c0));
    fma2(A1, wp, pk2(c1, c1));
  }
  *(float2*)(g_Q + (size_t)b0*CLIPD + col) = upk2(A0);
  *(float2*)(g_Q + (size_t)b1*CLIPD + col) = upk2(A1);
}

// ============ K2: qk[b,h,c] = sum_d Wk[c,h*64+d]*Q[b,h*64+d] / (8*temp) ============
// grid 128 (one b per CTA), 256 thr; warp w handles rows c = w, w+8, ...
// Lane loads float4 chunk k at d = lane*4 + k*128 -> head = 2k + (lane>=16).
__global__ void __launch_bounds__(256) k2_qk(const float* __restrict__ Wk,
                                             const float* __restrict__ temp){
  __shared__ float Qs[CLIPD];
  int t = threadIdx.x, wid = t>>5, lane = t&31;
  int b = blockIdx.x;
  for(int i = t; i < CLIPD; i += 256) Qs[i] = g_Q[(size_t)b*CLIPD + i];
  __syncthreads();
  float inv_scale = 1.0f/(8.0f*temp[0]);
  float q4x[4], q4y[4], q4z[4], q4w[4];
  #pragma unroll
  for(int k = 0; k < 4; k++){
    float4 q = *(const float4*)(Qs + lane*4 + k*128);
    q4x[k]=q.x; q4y[k]=q.y; q4z[k]=q.z; q4w[k]=q.w;
  }
  int hb = lane >> 4;
  for(int c = wid; c < DINOD; c += 8){
    const float4* wr = (const float4*)(Wk + (size_t)c*CLIPD);
    float s[4];
    #pragma unroll
    for(int k = 0; k < 4; k++){
      float4 w4 = wr[lane + k*32];
      s[k] = w4.x*q4x[k] + w4.y*q4y[k] + w4.z*q4z[k] + w4.w*q4w[k];
    }
    #pragma unroll
    for(int o = 8; o; o >>= 1){
      #pragma unroll
      for(int k = 0; k < 4; k++) s[k] += __shfl_xor_sync(0xffffffffu, s[k], o);
    }
    if((lane & 15) == 0){
      #pragma unroll
      for(int k = 0; k < 4; k++)
        g_qk[((size_t)b*NH + 2*k + hb)*DINOD + c] = s[k]*inv_scale;
    }
  }
}

// ============ K3a: raw logits[b][h][n] ============
// grid 1408 = 128 b x 11 slices(128 tokens); 256 thr.
// Warp w: head pair hp=w&3 (heads 2hp,2hp+1), token group tg=w>>2 (64 tokens).
// Full-warp c-split: lane owns float4 at c = lane*4 + j*128, j=0..2.
// Unroll 2 tokens -> 6 independent LDG.128 in flight per warp.
__global__ void __launch_bounds__(256) k3a_logits(const float* __restrict__ dino){
  int t = threadIdx.x, wid = t>>5, lane = t&31;
  int b = blockIdx.x / ASL, slice = blockIdx.x % ASL;
  int n0 = slice*128 + (wid>>2)*64;
  int h0 = 2*(wid & 3);
  const float* dino_b = dino + (size_t)b*NTOK*DINOD;

  unsigned long long q0[3][2], q1[3][2];
  {
    const float* qkb = g_qk + ((size_t)b*NH + h0)*DINOD;
    #pragma unroll
    for(int j = 0; j < 3; j++){
      float4 v = *(const float4*)(qkb + j*128 + lane*4);
      q0[j][0] = pk2(v.x,v.y); q0[j][1] = pk2(v.z,v.w);
      float4 u = *(const float4*)(qkb + DINOD + j*128 + lane*4);
      q1[j][0] = pk2(u.x,u.y); q1[j][1] = pk2(u.z,u.w);
    }
  }
  float* att0 = g_att + ((size_t)b*NH + h0)*NTOKP;
  float* att1 = att0 + NTOKP;

  for(int k = 0; k < 64; k += 2){
    int nA = n0 + k;
    if(nA >= NTOK) break;                       // warp-uniform
    bool vB = (nA + 1 < NTOK);
    const float4* rA = (const float4*)(dino_b + (size_t)nA*DINOD);
    const float4* rB = rA + 96;
    float4 a0 = rA[lane], a1 = rA[32+lane], a2 = rA[64+lane];
    float4 b0, b1, b2;
    if(vB){ b0 = rB[lane]; b1 = rB[32+lane]; b2 = rB[64+lane]; }
    else  { b0 = b1 = b2 = make_float4(0.f,0.f,0.f,0.f); }

    unsigned long long sA0=0ull, sA1=0ull, sB0=0ull, sB1=0ull;
    {
      unsigned long long dx, dy;
      dx = pk2(a0.x,a0.y); dy = pk2(a0.z,a0.w);
      fma2(sA0,dx,q0[0][0]); fma2(sA0,dy,q0[0][1]);
      fma2(sA1,dx,q1[0][0]); fma2(sA1,dy,q1[0][1]);
      dx = pk2(a1.x,a1.y); dy = pk2(a1.z,a1.w);
      fma2(sA0,dx,q0[1][0]); fma2(sA0,dy,q0[1][1]);
      fma2(sA1,dx,q1[1][0]); fma2(sA1,dy,q1[1][1]);
      dx = pk2(a2.x,a2.y); dy = pk2(a2.z,a2.w);
      fma2(sA0,dx,q0[2][0]); fma2(sA0,dy,q0[2][1]);
      fma2(sA1,dx,q1[2][0]); fma2(sA1,dy,q1[2][1]);
      dx = pk2(b0.x,b0.y); dy = pk2(b0.z,b0.w);
      fma2(sB0,dx,q0[0][0]); fma2(sB0,dy,q0[0][1]);
      fma2(sB1,dx,q1[0][0]); fma2(sB1,dy,q1[0][1]);
      dx = pk2(b1.x,b1.y); dy = pk2(b1.z,b1.w);
      fma2(sB0,dx,q0[1][0]); fma2(sB0,dy,q0[1][1]);
      fma2(sB1,dx,q1[1][0]); fma2(sB1,dy,q1[1][1]);
      dx = pk2(b2.x,b2.y); dy = pk2(b2.z,b2.w);
      fma2(sB0,dx,q0[2][0]); fma2(sB0,dy,q0[2][1]);
      fma2(sB1,dx,q1[2][0]); fma2(sB1,dy,q1[2][1]);
    }
    float2 P;
    P = upk2(sA0); float fA0 = P.x + P.y;
    P = upk2(sA1); float fA1 = P.x + P.y;
    P = upk2(sB0); float fB0 = P.x + P.y;
    P = upk2(sB1); float fB1 = P.x + P.y;
    #pragma unroll
    for(int o = 16; o; o >>= 1){
      fA0 += __shfl_xor_sync(0xffffffffu, fA0, o);
      fA1 += __shfl_xor_sync(0xffffffffu, fA1, o);
      fB0 += __shfl_xor_sync(0xffffffffu, fB0, o);
      fB1 += __shfl_xor_sync(0xffffffffu, fB1, o);
    }
    if(lane == 0){
      att0[nA] = fA0; att1[nA] = fA1;
      if(vB){ att0[nA+1] = fB0; att1[nA+1] = fB1; }
    }
  }
}

// ============ K3b: per-(b,h) max m and denom l ============
// grid 128, 256 thr; warp w owns head w. Two passes, L1-hot second pass.
__global__ void __launch_bounds__(256) k3b_ml(){
  int t = threadIdx.x, wid = t>>5, lane = t&31;
  int b = blockIdx.x;
  const float* row = g_att + ((size_t)b*NH + wid)*NTOKP;
  const float4* r4 = (const float4*)row;
  float mx = -1e30f;
  #pragma unroll 4
  for(int i = lane; i < 342; i += 32){        // n < 1368
    float4 v = r4[i];
    mx = fmaxf(mx, fmaxf(fmaxf(v.x, v.y), fmaxf(v.z, v.w)));
  }
  if(lane == 0) mx = fmaxf(mx, row[1368]);
  #pragma unroll
  for(int o = 16; o; o >>= 1) mx = fmaxf(mx, __shfl_xor_sync(0xffffffffu, mx, o));
  float m = mx;
  float s = 0.0f;
  #pragma unroll 4
  for(int i = lane; i < 342; i += 32){
    float4 v = r4[i];
    s += __expf(v.x - m) + __expf(v.y - m) + __expf(v.z - m) + __expf(v.w - m);
  }
  if(lane == 0) s += __expf(row[1368] - m);
  #pragma unroll
  for(int o = 16; o; o >>= 1) s += __shfl_xor_sync(0xffffffffu, s, o);
  if(lane == 0){
    g_ml[b*16 + wid]     = m;
    g_ml[b*16 + 8 + wid] = s;
  }
}

// ============ K3c: partial ctx[s][b][c][h] = sum_n exp(lg-m)*dino[b][n][c] ============
// grid 1024 = 128 b x 8 slices; 384 thr (thread owns column t); exp'ed slice in smem.
__global__ void __launch_bounds__(384) k3c_ctx(const float* __restrict__ dino){
  __shared__ float ea[SLTOK*NH];      // exp(lg - m), layout [n][h]
  __shared__ float m8[NH];
  int t = threadIdx.x;
  int b = blockIdx.x >> 3, slice = blockIdx.x & 7;
  int n0 = slice*SLTOK;
  int cnt = (slice == 7) ? (NTOK - 7*SLTOK) : SLTOK;
  if(t < NH) m8[t] = g_ml[b*16 + t];
  __syncthreads();
  for(int i = t; i < cnt*NH; i += 384){
    int n = i >> 3, h = i & 7;
    ea[i] = __expf(g_att[((size_t)b*NH + h)*NTOKP + n0 + n] - m8[h]);
  }
  __syncthreads();

  const float* dcol = dino + ((size_t)b*NTOK + n0)*DINOD + t;
  unsigned long long A0=0ull, A1=0ull, A2=0ull, A3=0ull;
  int n = 0;
  for(; n + 4 <= cnt; n += 4){
    float d0 = dcol[(size_t)(n+0)*DINOD];
    float d1 = dcol[(size_t)(n+1)*DINOD];
    float d2 = dcol[(size_t)(n+2)*DINOD];
    float d3 = dcol[(size_t)(n+3)*DINOD];
    ulonglong2 eL, eH;
    unsigned long long dd;
    eL = *(const ulonglong2*)(ea + (n+0)*NH); eH = *(const ulonglong2*)(ea + (n+0)*NH + 4);
    dd = pk2(d0,d0);
    fma2(A0, eL.x, dd); fma2(A1, eL.y, dd); fma2(A2, eH.x, dd); fma2(A3, eH.y, dd);
    eL = *(const ulonglong2*)(ea + (n+1)*NH); eH = *(const ulonglong2*)(ea + (n+1)*NH + 4);
    dd = pk2(d1,d1);
    fma2(A0, eL.x, dd); fma2(A1, eL.y, dd); fma2(A2, eH.x, dd); fma2(A3, eH.y, dd);
    eL = *(const ulonglong2*)(ea + (n+2)*NH); eH = *(const ulonglong2*)(ea + (n+2)*NH + 4);
    dd = pk2(d2,d2);
    fma2(A0, eL.x, dd); fma2(A1, eL.y, dd); fma2(A2, eH.x, dd); fma2(A3, eH.y, dd);
    eL = *(const ulonglong2*)(ea + (n+3)*NH); eH = *(const ulonglong2*)(ea + (n+3)*NH + 4);
    dd = pk2(d3,d3);
    fma2(A0, eL.x, dd); fma2(A1, eL.y, dd); fma2(A2, eH.x, dd); fma2(A3, eH.y, dd);
  }
  for(; n < cnt; n++){
    float d0 = dcol[(size_t)n*DINOD];
    ulonglong2 eL = *(const ulonglong2*)(ea + n*NH);
    ulonglong2 eH = *(const ulonglong2*)(ea + n*NH + 4);
    unsigned long long dd = pk2(d0,d0);
    fma2(A0, eL.x, dd); fma2(A1, eL.y, dd); fma2(A2, eH.x, dd); fma2(A3, eH.y, dd);
  }
  float* pb = g_part + ((size_t)(slice*BB + b))*DINOD*NH + (size_t)t*NH;
  float2 p0 = upk2(A0), p1 = upk2(A1), p2 = upk2(A2), p3 = upk2(A3);
  ((float4*)pb)[0] = make_float4(p0.x, p0.y, p1.x, p1.y);
  ((float4*)pb)[1] = make_float4(p2.x, p2.y, p3.x, p3.y);
}

// ============ K4: merge partials (scaled by 1/l), out = ctx @ Wv + bv, LayerNorm ============
__global__ void __launch_bounds__(1024) k4_out(const float* __restrict__ Wv,
                                               const float* __restrict__ bv,
                                               const float* __restrict__ gamma,
                                               const float* __restrict__ beta,
                                               float* __restrict__ out){
  __shared__ float cs[DINOD*NH];   // ctx, layout [c][h]
  __shared__ float red2[CLIPD];
  __shared__ float redS[16], redQ[16];
  __shared__ float stats[2];
  __shared__ float sinv[NH];
  int t = threadIdx.x;
  int b = blockIdx.x;
  if(t < NH) sinv[t] = 1.0f / g_ml[b*16 + 8 + t];
  __syncthreads();
  for(int i = t; i < DINOD*NH; i += 1024){
    float a = 0.0f;
    #pragma unroll
    for(int s = 0; s < NSL; s++)
      a += g_part[((size_t)(s*BB + b))*DINOD*NH + i];
    cs[i] = a * sinv[i & 7];
  }
  __syncthreads();
  int cg = t >> 9, col = t & 511, h = col >> 6;
  float acc = cg ? 0.0f : bv[col];
  {
    int c0 = cg*192;
    const float* wp = Wv + (size_t)c0*CLIPD + col;
    const float* cp = cs + c0*NH + h;
    #pragma unroll 8
    for(int c = 0; c < 192; c++)
      acc = fmaf(cp[c*NH], wp[(size_t)c*CLIPD], acc);
  }
  if(cg) red2[col] = acc;
  __syncthreads();
  float a = 0.0f;
  if(!cg){
    a = acc + red2[col];
    float s = a, q = a*a;
    #pragma unroll
    for(int o = 16; o; o >>= 1){
      s += __shfl_xor_sync(0xffffffffu, s, o);
      q += __shfl_xor_sync(0xffffffffu, q, o);
    }
    if((t&31) == 0){ redS[t>>5] = s; redQ[t>>5] = q; }
  }
  __syncthreads();
  if(t < 32){
    float v = (t < 16) ? redS[t] : redQ[t-16];
    #pragma unroll
    for(int o = 8; o; o >>= 1) v += __shfl_xor_sync(0xffffffffu, v, o);
    if(t == 0)  stats[0] = v;
    if(t == 16) stats[1] = v;
  }
  __syncthreads();
  if(!cg){
    float mu = stats[0]*(1.0f/512.0f);
    float var = stats[1]*(1.0f/512.0f) - mu*mu;
    float rstd = rsqrtf(var + 1e-5f);
    out[(size_t)b*CLIPD + col] = (a - mu)*rstd*gamma[col] + beta[col];
  }
}

extern "C" void kernel_launch(void* const* d_in, const int* in_sizes, int n_in,
                              void* d_out, int out_size) {
  const float* dino  = (const float*)d_in[0];
  const float* clip  = (const float*)d_in[1];
  const float* Wq    = (const float*)d_in[2];
  const float* bq    = (const float*)d_in[3];
  const float* Wk    = (const float*)d_in[4];
  // d_in[5] = bk: cancels in softmax
  const float* Wv    = (const float*)d_in[6];
  const float* bv    = (const float*)d_in[7];
  const float* temp  = (const float*)d_in[8];
  const float* gamma = (const float*)d_in[9];
  const float* beta  = (const float*)d_in[10];
  float* out = (float*)d_out;

  k1_qproj<<<128, 128>>>(clip, Wq, bq);
  k2_qk<<<128, 256>>>(Wk, temp);
  k3a_logits<<<BB*ASL, 256>>>(dino);
  k3b_ml<<<BB, 256>>>();
  k3c_ctx<<<BB*NSL, 384>>>(dino);
  k4_out<<<BB, 1024>>>(Wv, bv, gamma, beta, out);
}

// round 10
// speedup vs baseline: 1.1651x; 1.0598x over previous
#include <cuda_runtime.h>
#include <cuda_bf16.h>

#define BB     128
#define NTOK   1369
#define DINOD  384
#define CLIPD  512
#define NH     8
#define SPLIT0 685              // tokens in half 0 (half 1 = 684)
#define TILE   24               // tokens per chunk
#define CHUNKS 29               // ceil(685/24) = ceil(684/24) = 29
#define RSTRF  388              // padded row stride in floats (97 float4)
#define RSTR4  97               // padded row stride in float4

// k3 smem layout (floats)
#define OFF_DS0  0
#define OFF_DS1  (TILE*RSTRF)             // 9312
#define OFF_QS   (2*TILE*RSTRF)           // 18624  (8 rows x 97 f4)
#define OFF_CTX  (OFF_QS + NH*RSTRF)      // 21728  (384 cols x 8 heads)
#define OFF_LG   (OFF_CTX + DINOD*NH)     // 24800  (24 x 8)
#define OFF_WS   (OFF_LG + TILE*NH)       // 24992  (24 x 8)
#define OFF_MS   (OFF_WS + TILE*NH)       // 25184
#define OFF_LS   (OFF_MS + 8)             // 25192
#define OFF_RS   (OFF_LS + 8)             // 25200
#define SMEM3    ((OFF_RS + 8)*4)         // 100832 bytes

__device__ __align__(16) float g_Q[BB*CLIPD];
__device__ __align__(16) float g_qk[BB*NH*DINOD];
__device__ __align__(16) float g_ctx2[BB*2*DINOD*NH];   // raw ctx per (b,half), layout [c][h]
__device__ __align__(16) float g_ml[BB*2*16];           // per (b,half): m[0..7], l[8..15]

// ---- packed f32x2 helpers ----
__device__ __forceinline__ unsigned long long pk2(float x, float y){
  unsigned long long r; asm("mov.b64 %0, {%1,%2};" : "=l"(r) : "f"(x), "f"(y)); return r;
}
__device__ __forceinline__ float2 upk2(unsigned long long v){
  float2 r; asm("mov.b64 {%0,%1}, %2;" : "=f"(r.x), "=f"(r.y) : "l"(v)); return r;
}
__device__ __forceinline__ void fma2(unsigned long long& d, unsigned long long a, unsigned long long b){
  asm("fma.rn.f32x2 %0, %1, %2, %0;" : "+l"(d) : "l"(a), "l"(b));
}
__device__ __forceinline__ void mul2(unsigned long long& d, unsigned long long a){
  asm("mul.rn.f32x2 %0, %0, %1;" : "+l"(d) : "l"(a));
}
__device__ __forceinline__ void add2(unsigned long long& d, unsigned long long a){
  asm("add.rn.f32x2 %0, %0, %1;" : "+l"(d) : "l"(a));
}
__device__ __forceinline__ void cp16z(float* dst, const float* src, int sz){
  unsigned sa = (unsigned)__cvta_generic_to_shared(dst);
  asm volatile("cp.async.cg.shared.global [%0], [%1], 16, %2;" :: "r"(sa), "l"(src), "r"(sz) : "memory");
}

// ============ K1: Q = clip @ Wq + bq ============
__global__ void __launch_bounds__(128) k1_qproj(const float* __restrict__ clip,
                                                const float* __restrict__ Wq,
                                                const float* __restrict__ bq){
  __shared__ float cs[2][CLIPD];
  int t = threadIdx.x;
  int p = blockIdx.x >> 1, half = blockIdx.x & 1;
  int b0 = 2*p, b1 = 2*p + 1;
  for(int i = t; i < CLIPD; i += 128){
    cs[0][i] = clip[(size_t)b0*CLIPD + i];
    cs[1][i] = clip[(size_t)b1*CLIPD + i];
  }
  __syncthreads();
  int col = half*256 + 2*t;
  float2 bq2 = *(const float2*)(bq + col);
  unsigned long long A0 = pk2(bq2.x, bq2.y), A1 = A0;
  #pragma unroll 8
  for(int c = 0; c < CLIPD; c++){
    float2 w = *(const float2*)(Wq + (size_t)c*CLIPD + col);
    unsigned long long wp = pk2(w.x, w.y);
    float c0 = cs[0][c], c1 = cs[1][c];
    fma2(A0, wp, pk2(c0, c0));
    fma2(A1, wp, pk2(c1, c1));
  }
  *(float2*)(g_Q + (size_t)b0*CLIPD + col) = upk2(A0);
  *(float2*)(g_Q + (size_t)b1*CLIPD + col) = upk2(A1);
}

// ============ K2: qk[b,h,c] = sum_d Wk[c,h*64+d]*Q[b,h*64+d] / (8*temp) ============
__global__ void __launch_bounds__(256) k2_qk(const float* __restrict__ Wk,
                                             const float* __restrict__ temp){
  __shared__ float Qs[CLIPD];
  int t = threadIdx.x, wid = t>>5, lane = t&31;
  int b = blockIdx.x;
  for(int i = t; i < CLIPD; i += 256) Qs[i] = g_Q[(size_t)b*CLIPD + i];
  __syncthreads();
  float inv_scale = 1.0f/(8.0f*temp[0]);
  float q4x[4], q4y[4], q4z[4], q4w[4];
  #pragma unroll
  for(int k = 0; k < 4; k++){
    float4 q = *(const float4*)(Qs + lane*4 + k*128);
    q4x[k]=q.x; q4y[k]=q.y; q4z[k]=q.z; q4w[k]=q.w;
  }
  int hb = lane >> 4;
  for(int c = wid; c < DINOD; c += 8){
    const float4* wr = (const float4*)(Wk + (size_t)c*CLIPD);
    float s[4];
    #pragma unroll
    for(int k = 0; k < 4; k++){
      float4 w4 = wr[lane + k*32];
      s[k] = w4.x*q4x[k] + w4.y*q4y[k] + w4.z*q4z[k] + w4.w*q4w[k];
    }
    #pragma unroll
    for(int o = 8; o; o >>= 1){
      #pragma unroll
      for(int k = 0; k < 4; k++) s[k] += __shfl_xor_sync(0xffffffffu, s[k], o);
    }
    if((lane & 15) == 0){
      #pragma unroll
      for(int k = 0; k < 4; k++)
        g_qk[((size_t)b*NH + 2*k + hb)*DINOD + c] = s[k]*inv_scale;
    }
  }
}

// helper: async-load one chunk (TILE token rows) into padded smem buffer
__device__ __forceinline__ void load_chunk(float* dst, const float* dino_b,
                                           int row0, int cnt, int t){
  #pragma unroll
  for(int k = 0; k < 9; k++){
    int gi = t + k*256;              // 0..2303 (24*96 f4)
    int row = gi / 96;
    int col4 = gi - row*96;
    int tok = row0 + row;
    int sz = (tok < cnt) ? 16 : 0;
    cp16z(dst + row*RSTRF + col4*4, dino_b + (size_t)tok*DINOD + col4*4, sz);
  }
}

// ============ K3: fused streaming single-query attention ============
// grid 256 = 128 b x 2 token-halves; 256 thr; 2 CTAs/SM.
// Phase A: lane = head(3b) | token-sub(2b); thread owns full (token,head) dot.
// Phase B: thread owns dino column(s); ctx accumulated in SMEM with rescale.
__global__ void __launch_bounds__(256, 2) k3_attn(const float* __restrict__ dino){
  extern __shared__ float sm[];
  float* lg  = sm + OFF_LG;
  float* wsm = sm + OFF_WS;
  float* m_s = sm + OFF_MS;
  float* l_s = sm + OFF_LS;
  float* r_s = sm + OFF_RS;

  int t = threadIdx.x, wid = t>>5, lane = t&31;
  int cta = blockIdx.x, b = cta>>1, half = cta&1;
  int cnt = half ? (NTOK - SPLIT0) : SPLIT0;
  const float* dino_b = dino + ((size_t)b*NTOK + (half ? SPLIT0 : 0))*DINOD;

  // load qk into padded smem rows
  {
    const float4* src = (const float4*)(g_qk + (size_t)b*NH*DINOD);
    for(int i = t; i < NH*96; i += 256){
      int h = i / 96, j = i - h*96;
      *(float4*)(sm + OFF_QS + h*RSTRF + j*4) = src[i];
    }
  }
  // init ctx / stats
  for(int i = t; i < DINOD*NH; i += 256) sm[OFF_CTX + i] = 0.0f;
  if(t < 8){ m_s[t] = -1e30f; l_s[t] = 0.0f; }

  // prologue: chunk 0
  load_chunk(sm + OFF_DS0, dino_b, 0, cnt, t);
  asm volatile("cp.async.commit_group;" ::: "memory");
  __syncthreads();   // qs/ctx ready

  int h = lane & 7, ts = lane >> 3;
  int tok = wid*4 + ts;              // valid for wid < 6
  const float4* qsr = (const float4*)(sm + OFF_QS) + h*RSTR4;

  for(int i = 0; i < CHUNKS; i++){
    if(i+1 < CHUNKS)
      load_chunk(sm + OFF_DS0 + ((i+1)&1)*(TILE*RSTRF), dino_b, (i+1)*TILE, cnt, t);
    asm volatile("cp.async.commit_group;" ::: "memory");
    asm volatile("cp.async.wait_group 1;" ::: "memory");   // chunk i landed
    __syncthreads();

    float* dcur = sm + OFF_DS0 + (i&1)*(TILE*RSTRF);
    int base = i*TILE;
    int cn = (i == CHUNKS-1) ? (cnt - base) : TILE;

    // ---- Phase A: warp w<6 -> tokens w*4..w*4+3, all 8 heads via lanes ----
    if(wid < 6){
      const float4* dr = (const float4*)dcur + tok*RSTR4;
      unsigned long long A0 = 0ull, A1 = 0ull;
      #pragma unroll 8
      for(int j = 0; j < 96; j++){
        float4 d = dr[j];
        float4 q = qsr[j];
        fma2(A0, pk2(d.x,d.y), pk2(q.x,q.y));
        fma2(A1, pk2(d.z,d.w), pk2(q.z,q.w));
      }
      float2 pa = upk2(A0), pb = upk2(A1);
      float s = pa.x + pa.y + pb.x + pb.y;
      lg[tok*NH + h] = (base + tok < cnt) ? s : -1e30f;
    }
    __syncthreads();
    // ---- per-head max (warp w -> head w) ----
    {
      float v = (lane < TILE) ? lg[lane*NH + wid] : -1e30f;
      #pragma unroll
      for(int o = 16; o; o >>= 1) v = fmaxf(v, __shfl_xor_sync(0xffffffffu, v, o));
      if(lane == 0){
        float mo = m_s[wid];
        float mn = fmaxf(mo, v);
        r_s[wid] = __expf(mo - mn);
        m_s[wid] = mn;
      }
    }
    __syncthreads();
    if(t < TILE*NH) wsm[t] = __expf(lg[t] - m_s[t & 7]);
    __syncthreads();
    // ---- l update (parallel with Phase B) ----
    {
      float v = (lane < TILE) ? wsm[lane*NH + wid] : 0.0f;
      #pragma unroll
      for(int o = 16; o; o >>= 1) v += __shfl_xor_sync(0xffffffffu, v, o);
      if(lane == 0) l_s[wid] = l_s[wid]*r_s[wid] + v;
    }
    // ---- Phase B: ctx[c][h] = ctx*r + sum_n w[n][h]*d[n][c], ctx in smem ----
    ulonglong2 ra = *(const ulonglong2*)r_s;
    ulonglong2 rb = *(const ulonglong2*)(r_s + 4);
    #pragma unroll
    for(int pass = 0; pass < 2; pass++){
      int c = t + pass*256;
      if(pass == 1 && t >= 128) break;
      unsigned long long B0=0ull, B1=0ull, B2=0ull, B3=0ull;
      const float* dc = dcur + c;
      #pragma unroll 4
      for(int n = 0; n < cn; n++){
        float dv = dc[n*RSTRF];
        unsigned long long dd = pk2(dv, dv);
        ulonglong2 wa = *(const ulonglong2*)(wsm + n*NH);
        ulonglong2 wb = *(const ulonglong2*)(wsm + n*NH + 4);
        fma2(B0, wa.x, dd); fma2(B1, wa.y, dd);
        fma2(B2, wb.x, dd); fma2(B3, wb.y, dd);
      }
      float* cx = sm + OFF_CTX + c*NH;
      ulonglong2 c01 = *(ulonglong2*)cx;
      ulonglong2 c23 = *(ulonglong2*)(cx + 4);
      mul2(c01.x, ra.x); add2(c01.x, B0);
      mul2(c01.y, ra.y); add2(c01.y, B1);
      mul2(c23.x, rb.x); add2(c23.x, B2);
      mul2(c23.y, rb.y); add2(c23.y, B3);
      *(ulonglong2*)cx = c01;
      *(ulonglong2*)(cx + 4) = c23;
    }
    __syncthreads();   // ctx/wsm/buffer reuse fence for next chunk
  }

  // write raw ctx + (m, l)
  float* cb = g_ctx2 + (size_t)cta*DINOD*NH;
  for(int i = t; i < DINOD*NH; i += 256) cb[i] = sm[OFF_CTX + i];
  if(t < 8){
    g_ml[cta*16 + t]     = m_s[t];
    g_ml[cta*16 + 8 + t] = l_s[t];
  }
}

// ============ K4: merge halves, out = ctx @ Wv + bv, LayerNorm ============
__global__ void __launch_bounds__(1024) k4_out(const float* __restrict__ Wv,
                                               const float* __restrict__ bv,
                                               const float* __restrict__ gamma,
                                               const float* __restrict__ beta,
                                               float* __restrict__ out){
  __shared__ float cs[DINOD*NH];   // merged normalized ctx, layout [c][h]
  __shared__ float red2[CLIPD];
  __shared__ float redS[16], redQ[16];
  __shared__ float stats[2];
  __shared__ float sA[NH], sB[NH];
  int t = threadIdx.x;
  int b = blockIdx.x;
  if(t < NH){
    float mA = g_ml[(b*2)*16 + t],   lA = g_ml[(b*2)*16 + 8 + t];
    float mB = g_ml[(b*2+1)*16 + t], lB = g_ml[(b*2+1)*16 + 8 + t];
    float m  = fmaxf(mA, mB);
    float eA = __expf(mA - m), eB = __expf(mB - m);
    float inv = 1.0f/(lA*eA + lB*eB);
    sA[t] = eA*inv; sB[t] = eB*inv;
  }
  __syncthreads();
  const float* cA = g_ctx2 + (size_t)(b*2)*DINOD*NH;
  const float* cB = g_ctx2 + (size_t)(b*2+1)*DINOD*NH;
  for(int i = t; i < DINOD*NH; i += 1024)
    cs[i] = cA[i]*sA[i & 7] + cB[i]*sB[i & 7];
  __syncthreads();
  int cg = t >> 9, col = t & 511, h = col >> 6;
  float acc = cg ? 0.0f : bv[col];
  {
    int c0 = cg*192;
    const float* wp = Wv + (size_t)c0*CLIPD + col;
    const float* cp = cs + c0*NH + h;
    #pragma unroll 8
    for(int c = 0; c < 192; c++)
      acc = fmaf(cp[c*NH], wp[(size_t)c*CLIPD], acc);
  }
  if(cg) red2[col] = acc;
  __syncthreads();
  float a = 0.0f;
  if(!cg){
    a = acc + red2[col];
    float s = a, q = a*a;
    #pragma unroll
    for(int o = 16; o; o >>= 1){
      s += __shfl_xor_sync(0xffffffffu, s, o);
      q += __shfl_xor_sync(0xffffffffu, q, o);
    }
    if((t&31) == 0){ redS[t>>5] = s; redQ[t>>5] = q; }
  }
  __syncthreads();
  if(t < 32){
    float v = (t < 16) ? redS[t] : redQ[t-16];
    #pragma unroll
    for(int o = 8; o; o >>= 1) v += __shfl_xor_sync(0xffffffffu, v, o);
    if(t == 0)  stats[0] = v;
    if(t == 16) stats[1] = v;
  }
  __syncthreads();
  if(!cg){
    float mu = stats[0]*(1.0f/512.0f);
    float var = stats[1]*(1.0f/512.0f) - mu*mu;
    float rstd = rsqrtf(var + 1e-5f);
    out[(size_t)b*CLIPD + col] = (a - mu)*rstd*gamma[col] + beta[col];
  }
}

extern "C" void kernel_launch(void* const* d_in, const int* in_sizes, int n_in,
                              void* d_out, int out_size) {
  const float* dino  = (const float*)d_in[0];
  const float* clip  = (const float*)d_in[1];
  const float* Wq    = (const float*)d_in[2];
  const float* bq    = (const float*)d_in[3];
  const float* Wk    = (const float*)d_in[4];
  // d_in[5] = bk: cancels in softmax
  const float* Wv    = (const float*)d_in[6];
  const float* bv    = (const float*)d_in[7];
  const float* temp  = (const float*)d_in[8];
  const float* gamma = (const float*)d_in[9];
  const float* beta  = (const float*)d_in[10];
  float* out = (float*)d_out;

  cudaFuncSetAttribute(k3_attn, cudaFuncAttributeMaxDynamicSharedMemorySize, SMEM3);

  k1_qproj<<<128, 128>>>(clip, Wq, bq);
  k2_qk<<<128, 256>>>(Wk, temp);
  k3_attn<<<256, 256, SMEM3>>>(dino);
  k4_out<<<128, 1024>>>(Wv, bv, gamma, beta, out);
}

// round 11
// speedup vs baseline: 1.5317x; 1.3147x over previous
#include <cuda_runtime.h>
#include <cuda_bf16.h>

#define BB     128
#define NTOK   1369
#define DINOD  384
#define CLIPD  512
#define NH     8
#define TILE   32
#define CHUNKS 43                 // ceil(1369/32)
#define BUFF   (TILE*DINOD)       // 12288 floats per buffer

// k3 smem layout (floats)
#define OFF_QS  (2*BUFF)          // 24576 : qk 8*384
#define OFF_LG  (OFF_QS + NH*DINOD)   // 27648 : 32*8
#define OFF_WSM (OFF_LG + TILE*NH)    // 27904 : 32*8
#define OFF_RS  (OFF_WSM + TILE*NH)   // 28160 : 8
#define OFF_LS  (OFF_RS + 8)          // 28168 : 8
#define SMEM3   ((OFF_LS + 8)*4)      // 112704 bytes

__device__ __align__(16) float g_Q[BB*CLIPD];
__device__ __align__(16) float g_qk[BB*NH*DINOD];
__device__ __align__(16) float g_ctx[BB*DINOD*NH];   // normalized ctx, layout [b][c][h]

// ---- packed f32x2 helpers ----
__device__ __forceinline__ unsigned long long pk2(float x, float y){
  unsigned long long r; asm("mov.b64 %0, {%1,%2};" : "=l"(r) : "f"(x), "f"(y)); return r;
}
__device__ __forceinline__ float2 upk2(unsigned long long v){
  float2 r; asm("mov.b64 {%0,%1}, %2;" : "=f"(r.x), "=f"(r.y) : "l"(v)); return r;
}
__device__ __forceinline__ void fma2(unsigned long long& d, unsigned long long a, unsigned long long b){
  asm("fma.rn.f32x2 %0, %1, %2, %0;" : "+l"(d) : "l"(a), "l"(b));
}
__device__ __forceinline__ void mul2(unsigned long long& d, unsigned long long a){
  asm("mul.rn.f32x2 %0, %0, %1;" : "+l"(d) : "l"(a));
}
__device__ __forceinline__ void cp16z(float* dst, const float* src, int sz){
  unsigned sa = (unsigned)__cvta_generic_to_shared(dst);
  asm volatile("cp.async.cg.shared.global [%0], [%1], 16, %2;" :: "r"(sa), "l"(src), "r"(sz) : "memory");
}

// ============ K1: Q = clip @ Wq + bq ============
__global__ void __launch_bounds__(128) k1_qproj(const float* __restrict__ clip,
                                                const float* __restrict__ Wq,
                                                const float* __restrict__ bq){
  __shared__ float cs[2][CLIPD];
  int t = threadIdx.x;
  int p = blockIdx.x >> 1, half = blockIdx.x & 1;
  int b0 = 2*p, b1 = 2*p + 1;
  for(int i = t; i < CLIPD; i += 128){
    cs[0][i] = clip[(size_t)b0*CLIPD + i];
    cs[1][i] = clip[(size_t)b1*CLIPD + i];
  }
  __syncthreads();
  int col = half*256 + 2*t;
  float2 bq2 = *(const float2*)(bq + col);
  unsigned long long A0 = pk2(bq2.x, bq2.y), A1 = A0;
  #pragma unroll 8
  for(int c = 0; c < CLIPD; c++){
    float2 w = *(const float2*)(Wq + (size_t)c*CLIPD + col);
    unsigned long long wp = pk2(w.x, w.y);
    float c0 = cs[0][c], c1 = cs[1][c];
    fma2(A0, wp, pk2(c0, c0));
    fma2(A1, wp, pk2(c1, c1));
  }
  *(float2*)(g_Q + (size_t)b0*CLIPD + col) = upk2(A0);
  *(float2*)(g_Q + (size_t)b1*CLIPD + col) = upk2(A1);
}

// ============ K2: qk[b,h,c] = sum_d Wk[c,h*64+d]*Q[b,h*64+d] / (8*temp) ============
__global__ void __launch_bounds__(256) k2_qk(const float* __restrict__ Wk,
                                             const float* __restrict__ temp){
  __shared__ float Qs[CLIPD];
  int t = threadIdx.x, wid = t>>5, lane = t&31;
  int b = blockIdx.x;
  for(int i = t; i < CLIPD; i += 256) Qs[i] = g_Q[(size_t)b*CLIPD + i];
  __syncthreads();
  float inv_scale = 1.0f/(8.0f*temp[0]);
  float q4x[4], q4y[4], q4z[4], q4w[4];
  #pragma unroll
  for(int k = 0; k < 4; k++){
    float4 q = *(const float4*)(Qs + lane*4 + k*128);
    q4x[k]=q.x; q4y[k]=q.y; q4z[k]=q.z; q4w[k]=q.w;
  }
  int hb = lane >> 4;
  for(int c = wid; c < DINOD; c += 8){
    const float4* wr = (const float4*)(Wk + (size_t)c*CLIPD);
    float s[4];
    #pragma unroll
    for(int k = 0; k < 4; k++){
      float4 w4 = wr[lane + k*32];
      s[k] = w4.x*q4x[k] + w4.y*q4y[k] + w4.z*q4z[k] + w4.w*q4w[k];
    }
    #pragma unroll
    for(int o = 8; o; o >>= 1){
      #pragma unroll
      for(int k = 0; k < 4; k++) s[k] += __shfl_xor_sync(0xffffffffu, s[k], o);
    }
    if((lane & 15) == 0){
      #pragma unroll
      for(int k = 0; k < 4; k++)
        g_qk[((size_t)b*NH + 2*k + hb)*DINOD + c] = s[k]*inv_scale;
    }
  }
}

// async-load one 32-token chunk (zfill past NTOK)
__device__ __forceinline__ void load_chunk(float* dst, const float* dino_b, int tok0, int t){
  #pragma unroll
  for(int k = 0; k < 6; k++){
    int gi = t + k*512;              // 0..3071 float4s
    int row = gi / 96, c4 = gi - row*96;
    int tok = tok0 + row;
    cp16z(dst + row*DINOD + c4*4, dino_b + (size_t)tok*DINOD + c4*4, (tok < NTOK) ? 16 : 0);
  }
}

// ============ K3: fused streaming single-query attention ============
// grid 128 (one b per CTA), 512 thr, 1 CTA/SM (16 warps, <=128 regs).
// Phase A: thread tile 4 tok x 4 heads x 12 c; warp = 32 c-slices; butterfly reduce.
// Phase B: thread t<384 owns column t; ctx in 4 persistent f32x2 registers.
__global__ void __launch_bounds__(512, 1) k3_attn(const float* __restrict__ dino){
  extern __shared__ float sm[];
  int t = threadIdx.x, lane = t & 31, warp = t >> 5;
  int hh = warp & 1, tg = warp >> 1;   // head half, token group
  int b = blockIdx.x;
  const float* dino_b = dino + (size_t)b*NTOK*DINOD;

  // qk -> smem (contiguous [h][c])
  {
    const float4* src = (const float4*)(g_qk + (size_t)b*NH*DINOD);
    float4* dst = (float4*)(sm + OFF_QS);
    for(int i = t; i < NH*96; i += 512) dst[i] = src[i];
  }
  load_chunk(sm, dino_b, 0, t);
  asm volatile("cp.async.commit_group;" ::: "memory");

  unsigned long long A0=0ull, A1=0ull, A2=0ull, A3=0ull;   // ctx col t, head pairs
  float m_run = -1e30f, l_run = 0.0f;                       // per-lane copy, warp<8

  for(int i = 0; i < CHUNKS; i++){
    asm volatile("cp.async.wait_group 0;" ::: "memory");
    __syncthreads();                       // chunk i ready + prev Phase B done (+qs on i=0)
    if(i+1 < CHUNKS)
      load_chunk(sm + ((i+1)&1)*BUFF, dino_b, (i+1)*TILE, t);
    asm volatile("cp.async.commit_group;" ::: "memory");

    const float* dcur = sm + (i&1)*BUFF;
    int base = i*TILE;

    // ---- Phase A ----
    unsigned long long acc[16];
    #pragma unroll
    for(int m = 0; m < 16; m++) acc[m] = 0ull;
    {
      const float4* db = (const float4*)dcur;
      const float4* qb = (const float4*)(sm + OFF_QS);
      #pragma unroll
      for(int j = 0; j < 3; j++){
        unsigned long long dlo[4], dhi[4], qlo[4], qhi[4];
        #pragma unroll
        for(int k = 0; k < 4; k++){
          float4 d = db[(tg*4+k)*96 + lane + 32*j];
          dlo[k] = pk2(d.x, d.y); dhi[k] = pk2(d.z, d.w);
        }
        #pragma unroll
        for(int q = 0; q < 4; q++){
          float4 qq = qb[(hh*4+q)*96 + lane + 32*j];
          qlo[q] = pk2(qq.x, qq.y); qhi[q] = pk2(qq.z, qq.w);
        }
        #pragma unroll
        for(int k = 0; k < 4; k++)
          #pragma unroll
          for(int q = 0; q < 4; q++){
            fma2(acc[k*4+q], dlo[k], qlo[q]);
            fma2(acc[k*4+q], dhi[k], qhi[q]);
          }
      }
    }
    {
      float v[16];
      #pragma unroll
      for(int m = 0; m < 16; m++){ float2 p = upk2(acc[m]); v[m] = p.x + p.y; }
      // butterfly: 16 values across 32 lanes
      { bool hi = lane & 1;
        #pragma unroll
        for(int m = 0; m < 8; m++){ float s = hi ? v[m] : v[m+8];
          float r = __shfl_xor_sync(0xffffffffu, s, 1);
          v[m] = (hi ? v[m+8] : v[m]) + r; } }
      { bool hi = lane & 2;
        #pragma unroll
        for(int m = 0; m < 4; m++){ float s = hi ? v[m] : v[m+4];
          float r = __shfl_xor_sync(0xffffffffu, s, 2);
          v[m] = (hi ? v[m+4] : v[m]) + r; } }
      { bool hi = lane & 4;
        #pragma unroll
        for(int m = 0; m < 2; m++){ float s = hi ? v[m] : v[m+2];
          float r = __shfl_xor_sync(0xffffffffu, s, 4);
          v[m] = (hi ? v[m+2] : v[m]) + r; } }
      { bool hi = lane & 8;
        { float s = hi ? v[0] : v[1];
          float r = __shfl_xor_sync(0xffffffffu, s, 8);
          v[0] = (hi ? v[1] : v[0]) + r; } }
      v[0] += __shfl_xor_sync(0xffffffffu, v[0], 16);
      if(lane < 16){
        int idx = ((lane&1)*8) | (((lane>>1)&1)*4) | (((lane>>2)&1)*2) | ((lane>>3)&1);
        int tok = tg*4 + (idx>>2);
        int h   = hh*4 + (idx&3);
        sm[OFF_LG + tok*NH + h] = (base + tok < NTOK) ? v[0] : -1e30f;
      }
    }
    __syncthreads();
    // ---- softmax bookkeeping: warp h handles head h over 32 tokens ----
    if(warp < 8){
      float lgv = sm[OFF_LG + lane*NH + warp];
      float mx = lgv;
      #pragma unroll
      for(int o = 16; o; o >>= 1) mx = fmaxf(mx, __shfl_xor_sync(0xffffffffu, mx, o));
      float mn = fmaxf(m_run, mx);
      float r  = __expf(m_run - mn);
      m_run = mn;
      float wv = __expf(lgv - mn);
      float ls = wv;
      #pragma unroll
      for(int o = 16; o; o >>= 1) ls += __shfl_xor_sync(0xffffffffu, ls, o);
      l_run = l_run*r + ls;
      sm[OFF_WSM + lane*NH + warp] = wv;
      if(lane == 0){ sm[OFF_RS + warp] = r; sm[OFF_LS + warp] = l_run; }
    }
    __syncthreads();
    // ---- Phase B: ctx update in registers ----
    if(t < DINOD){
      ulonglong2 ra = *(const ulonglong2*)(sm + OFF_RS);
      ulonglong2 rb = *(const ulonglong2*)(sm + OFF_RS + 4);
      mul2(A0, ra.x); mul2(A1, ra.y); mul2(A2, rb.x); mul2(A3, rb.y);
      const float* dc = dcur + t;
      #pragma unroll 4
      for(int n = 0; n < TILE; n++){
        float dv = dc[n*DINOD];
        unsigned long long dd = pk2(dv, dv);
        ulonglong2 wa = *(const ulonglong2*)(sm + OFF_WSM + n*NH);
        ulonglong2 wb = *(const ulonglong2*)(sm + OFF_WSM + n*NH + 4);
        fma2(A0, wa.x, dd); fma2(A1, wa.y, dd);
        fma2(A2, wb.x, dd); fma2(A3, wb.y, dd);
      }
    }
  }

  // normalize and store ctx
  if(t < DINOD){
    float4 l0 = *(const float4*)(sm + OFF_LS);
    float4 l1 = *(const float4*)(sm + OFF_LS + 4);
    unsigned long long i01 = pk2(1.0f/l0.x, 1.0f/l0.y);
    unsigned long long i23 = pk2(1.0f/l0.z, 1.0f/l0.w);
    unsigned long long i45 = pk2(1.0f/l1.x, 1.0f/l1.y);
    unsigned long long i67 = pk2(1.0f/l1.z, 1.0f/l1.w);
    mul2(A0, i01); mul2(A1, i23); mul2(A2, i45); mul2(A3, i67);
    float2 p0 = upk2(A0), p1 = upk2(A1), p2 = upk2(A2), p3 = upk2(A3);
    float* dst = g_ctx + ((size_t)b*DINOD + t)*NH;
    ((float4*)dst)[0] = make_float4(p0.x, p0.y, p1.x, p1.y);
    ((float4*)dst)[1] = make_float4(p2.x, p2.y, p3.x, p3.y);
  }
}

// ============ K4: out = ctx @ Wv + bv, LayerNorm ============
__global__ void __launch_bounds__(1024) k4_out(const float* __restrict__ Wv,
                                               const float* __restrict__ bv,
                                               const float* __restrict__ gamma,
                                               const float* __restrict__ beta,
                                               float* __restrict__ out){
  __shared__ float cs[DINOD*NH];   // ctx, layout [c][h]
  __shared__ float red2[CLIPD];
  __shared__ float redS[16], redQ[16];
  __shared__ float stats[2];
  int t = threadIdx.x;
  int b = blockIdx.x;
  for(int i = t; i < DINOD*NH; i += 1024)
    cs[i] = g_ctx[(size_t)b*DINOD*NH + i];
  __syncthreads();
  int cg = t >> 9, col = t & 511, h = col >> 6;
  float acc = cg ? 0.0f : bv[col];
  {
    int c0 = cg*192;
    const float* wp = Wv + (size_t)c0*CLIPD + col;
    const float* cp = cs + c0*NH + h;
    #pragma unroll 8
    for(int c = 0; c < 192; c++)
      acc = fmaf(cp[c*NH], wp[(size_t)c*CLIPD], acc);
  }
  if(cg) red2[col] = acc;
  __syncthreads();
  float a = 0.0f;
  if(!cg){
    a = acc + red2[col];
    float s = a, q = a*a;
    #pragma unroll
    for(int o = 16; o; o >>= 1){
      s += __shfl_xor_sync(0xffffffffu, s, o);
      q += __shfl_xor_sync(0xffffffffu, q, o);
    }
    if((t&31) == 0){ redS[t>>5] = s; redQ[t>>5] = q; }
  }
  __syncthreads();
  if(t < 32){
    float v = (t < 16) ? redS[t] : redQ[t-16];
    #pragma unroll
    for(int o = 8; o; o >>= 1) v += __shfl_xor_sync(0xffffffffu, v, o);
    if(t == 0)  stats[0] = v;
    if(t == 16) stats[1] = v;
  }
  __syncthreads();
  if(!cg){
    float mu = stats[0]*(1.0f/512.0f);
    float var = stats[1]*(1.0f/512.0f) - mu*mu;
    float rstd = rsqrtf(var + 1e-5f);
    out[(size_t)b*CLIPD + col] = (a - mu)*rstd*gamma[col] + beta[col];
  }
}

extern "C" void kernel_launch(void* const* d_in, const int* in_sizes, int n_in,
                              void* d_out, int out_size) {
  const float* dino  = (const float*)d_in[0];
  const float* clip  = (const float*)d_in[1];
  const float* Wq    = (const float*)d_in[2];
  const float* bq    = (const float*)d_in[3];
  const float* Wk    = (const float*)d_in[4];
  // d_in[5] = bk: cancels in softmax
  const float* Wv    = (const float*)d_in[6];
  const float* bv    = (const float*)d_in[7];
  const float* temp  = (const float*)d_in[8];
  const float* gamma = (const float*)d_in[9];
  const float* beta  = (const float*)d_in[10];
  float* out = (float*)d_out;

  cudaFuncSetAttribute(k3_attn, cudaFuncAttributeMaxDynamicSharedMemorySize, SMEM3);

  k1_qproj<<<128, 128>>>(clip, Wq, bq);
  k2_qk<<<128, 256>>>(Wk, temp);
  k3_attn<<<BB, 512, SMEM3>>>(dino);
  k4_out<<<BB, 1024>>>(Wv, bv, gamma, beta, out);
}